// round 3
// baseline (speedup 1.0000x reference)
#include <cuda_runtime.h>
#include <cuda_bf16.h>
#include <cstdint>

#define NN 50000      // nodes
#define NE 500000     // edges
#define HD 128        // hidden dim
#define NL 3          // layers

// ---------------- scratch (device globals; no allocation allowed) ----------------
__device__ float g_es[(size_t)NE * 256];     // edge scratch: m_h [E,128] then a_h [E,256]
__device__ float g_m[(size_t)NE * 128];      // message output m [E,128]
__device__ float g_intra[(size_t)NN * 128];  // segment_sum(m) per node
__device__ float g_hnode[(size_t)NN * 256];  // node MLP hidden
__device__ float g_xA[(size_t)NN * 128];
__device__ float g_xB[(size_t)NN * 128];
__device__ float g_pos[NN * 3];
__device__ float g_posacc[NN * 3];
__device__ float g_deg[NN];
__device__ float g_invden[NN];
__device__ int   g_src[NE];
__device__ int   g_dst[NE];
__device__ int   g_is64;

// ---------------- index dtype detection + normalization ----------------
// If edge_index is int64 (little-endian), every odd 32-bit word is the zero
// high-half (all values in [0, 50000)). If it is int32, odd words are random
// node indices and are essentially never all zero across 128 samples.
__global__ void detect_idx_kernel(const int* __restrict__ ei) {
    int nz = 0;
    for (int i = 0; i < 128; i++)
        if (ei[2 * i + 1] != 0) nz++;
    g_is64 = (nz == 0) ? 1 : 0;
}

__global__ void cvt_idx_kernel(const int* __restrict__ ei,
                               int* __restrict__ srcO, int* __restrict__ dstO) {
    int e = blockIdx.x * blockDim.x + threadIdx.x;
    if (e >= NE) return;
    if (g_is64) {
        srcO[e] = ei[2 * e];
        dstO[e] = ei[2 * NE + 2 * e];
    } else {
        srcO[e] = ei[e];
        dstO[e] = ei[NE + e];
    }
}

// ---------------- helpers ----------------
__global__ void zero_kernel(float* p, int n) {
    int i = blockIdx.x * blockDim.x + threadIdx.x;
    if (i < n) p[i] = 0.0f;
}

__global__ void deg_kernel(const int* __restrict__ dst, float* __restrict__ deg) {
    int e = blockIdx.x * blockDim.x + threadIdx.x;
    if (e < NE) atomicAdd(&deg[dst[e]], 1.0f);
}

__global__ void invden_kernel(const float* __restrict__ deg, float* __restrict__ invden) {
    int n = blockIdx.x * blockDim.x + threadIdx.x;
    if (n < NN) invden[n] = 1.0f / fmaxf(deg[n], 1.0f);
}

__global__ void posupd_kernel(const float* __restrict__ posacc,
                              const float* __restrict__ invden,
                              float* __restrict__ pos) {
    int i = blockIdx.x * blockDim.x + threadIdx.x;
    if (i < NN * 3) pos[i] += posacc[i] * invden[i / 3];
}

// scatter m[e,:] into intra[dst[e],:] (one warp per edge, 4 cols per lane)
__global__ void scatter_m_kernel(const float* __restrict__ m,
                                 const int* __restrict__ dst,
                                 float* __restrict__ intra) {
    int t = blockIdx.x * blockDim.x + threadIdx.x;
    int e = t >> 5;
    if (e >= NE) return;
    int c = (t & 31) * 4;
    float4 v = *(const float4*)(m + (size_t)e * 128 + c);
    float* p = intra + (size_t)dst[e] * 128 + c;
    atomicAdd(p + 0, v.x);
    atomicAdd(p + 1, v.y);
    atomicAdd(p + 2, v.z);
    atomicAdd(p + 3, v.w);
}

// w = a_h[e,:] . W2 + b2 ; acc_e = w * rel/dist ; atomic-accumulate into posacc[dst]
__global__ __launch_bounds__(256) void w_acc_kernel(
    const float* __restrict__ ah,        // [E,256]
    const float* __restrict__ W2,        // [256]
    const float* __restrict__ b2p,       // [1]
    const float* __restrict__ pos,       // [N,3]
    const int* __restrict__ srcI,
    const int* __restrict__ dstI,
    float* __restrict__ posacc)
{
    __shared__ float w2s[256];
    int tid = threadIdx.x;
    w2s[tid] = W2[tid];
    __syncthreads();
    int lane = tid & 31;
    int e = blockIdx.x * 8 + (tid >> 5);
    if (e >= NE) return;
    const float* row = ah + (size_t)e * 256;
    float s = 0.0f;
    #pragma unroll
    for (int k = 0; k < 256; k += 32) s += row[k + lane] * w2s[k + lane];
    #pragma unroll
    for (int o = 16; o; o >>= 1) s += __shfl_xor_sync(0xffffffffu, s, o);
    if (lane == 0) {
        float w = s + b2p[0];
        int sI = srcI[e], dI = dstI[e];
        float rx = pos[sI * 3 + 0] - pos[dI * 3 + 0];
        float ry = pos[sI * 3 + 1] - pos[dI * 3 + 1];
        float rz = pos[sI * 3 + 2] - pos[dI * 3 + 2];
        float d = sqrtf(rx * rx + ry * ry + rz * rz);
        float f = w / d;
        atomicAdd(&posacc[dI * 3 + 0], f * rx);
        atomicAdd(&posacc[dI * 3 + 1], f * ry);
        atomicAdd(&posacc[dI * 3 + 2], f * rz);
    }
}

// ---------------- generic fused-gather SGEMM ----------------
// C[M,N] = act(A'[M,K] @ B[K,N] + bias), 128x128x8 tiles, 8x8 microtiles.
// MODE 0: A' = A (row-major, lda=K)
// MODE 1: A'[e, k] = k<128 ? x[dst[e],k] : (k<256 ? x[src[e],k-128] : edge_attr[e,k-256])
// MODE 2: A'[n, k] = k<128 ? A[n,k] : intra[n,k-128]*invden[n]
template <int MODE, bool RELU>
__global__ __launch_bounds__(256) void gemm_kernel(
    int M, int K, int N,
    const float* __restrict__ A,
    const float* __restrict__ EA,
    const int* __restrict__ srcI,
    const int* __restrict__ dstI,
    const float* __restrict__ intra,
    const float* __restrict__ invden,
    const float* __restrict__ B,
    const float* __restrict__ bias,
    float* __restrict__ C)
{
    const int BM = 128, BN = 128, BK = 8;
    __shared__ float As[BK][BM];
    __shared__ float Bs[BK][BN];

    int tid = threadIdx.x;
    int brow = blockIdx.x * BM;
    int bcol = blockIdx.y * BN;

    int a_row = tid >> 1;        // 0..127
    int a_k4 = (tid & 1) * 4;    // 0 or 4
    int b_row = tid >> 5;        // 0..7
    int b_col4 = (tid & 31) * 4; // 0..124

    int ty = tid >> 4, tx = tid & 15;

    float acc[8][8];
    #pragma unroll
    for (int i = 0; i < 8; i++)
        #pragma unroll
        for (int j = 0; j < 8; j++) acc[i][j] = 0.0f;

    for (int kt = 0; kt < K; kt += BK) {
        float4 av = make_float4(0.f, 0.f, 0.f, 0.f);
        int grow = brow + a_row;
        if (grow < M) {
            int gk = kt + a_k4;
            if (MODE == 0) {
                av = *(const float4*)(A + (size_t)grow * K + gk);
            } else if (MODE == 1) {
                if (gk < HD) {
                    int r = dstI[grow];
                    av = *(const float4*)(A + (size_t)r * HD + gk);
                } else if (gk < 2 * HD) {
                    int r = srcI[grow];
                    av = *(const float4*)(A + (size_t)r * HD + (gk - HD));
                } else {
                    av = *(const float4*)(EA + (size_t)grow * HD + (gk - 2 * HD));
                }
            } else { // MODE 2
                if (gk < HD) {
                    av = *(const float4*)(A + (size_t)grow * HD + gk);
                } else {
                    float iv = invden[grow];
                    float4 t = *(const float4*)(intra + (size_t)grow * HD + (gk - HD));
                    av = make_float4(t.x * iv, t.y * iv, t.z * iv, t.w * iv);
                }
            }
        }
        As[a_k4 + 0][a_row] = av.x;
        As[a_k4 + 1][a_row] = av.y;
        As[a_k4 + 2][a_row] = av.z;
        As[a_k4 + 3][a_row] = av.w;

        float4 bv = *(const float4*)(B + (size_t)(kt + b_row) * N + bcol + b_col4);
        *(float4*)(&Bs[b_row][b_col4]) = bv;

        __syncthreads();

        #pragma unroll
        for (int kk = 0; kk < BK; kk++) {
            float ra[8], rb[8];
            #pragma unroll
            for (int i = 0; i < 8; i++) ra[i] = As[kk][ty * 8 + i];
            #pragma unroll
            for (int j = 0; j < 8; j++) rb[j] = Bs[kk][tx * 8 + j];
            #pragma unroll
            for (int i = 0; i < 8; i++)
                #pragma unroll
                for (int j = 0; j < 8; j++)
                    acc[i][j] = fmaf(ra[i], rb[j], acc[i][j]);
        }
        __syncthreads();
    }

    // epilogue
    float bb[8];
    #pragma unroll
    for (int j = 0; j < 8; j++) bb[j] = bias[bcol + tx * 8 + j];

    #pragma unroll
    for (int i = 0; i < 8; i++) {
        int row = brow + ty * 8 + i;
        if (row >= M) continue;
        float* crow = C + (size_t)row * N + bcol + tx * 8;
        #pragma unroll
        for (int j = 0; j < 8; j += 4) {
            float4 v;
            v.x = acc[i][j + 0] + bb[j + 0];
            v.y = acc[i][j + 1] + bb[j + 1];
            v.z = acc[i][j + 2] + bb[j + 2];
            v.w = acc[i][j + 3] + bb[j + 3];
            if (RELU) {
                v.x = fmaxf(v.x, 0.f);
                v.y = fmaxf(v.y, 0.f);
                v.z = fmaxf(v.z, 0.f);
                v.w = fmaxf(v.w, 0.f);
            }
            *(float4*)(crow + j) = v;
        }
    }
}

// ---------------- host launch ----------------
extern "C" void kernel_launch(void* const* d_in, const int* in_sizes, int n_in,
                              void* d_out, int out_size) {
    const float* x_in   = (const float*)d_in[0];
    const int* ei_raw   = (const int*)d_in[1];   // int32 view; dtype resolved on device
    const float* ea     = (const float*)d_in[2];
    const float* pos_in = (const float*)d_in[3];
    const float* mW1 = (const float*)d_in[4];
    const float* mb1 = (const float*)d_in[5];
    const float* mW2 = (const float*)d_in[6];
    const float* mb2 = (const float*)d_in[7];
    const float* aW1 = (const float*)d_in[8];
    const float* ab1 = (const float*)d_in[9];
    const float* aW2 = (const float*)d_in[10];
    const float* ab2 = (const float*)d_in[11];
    const float* nW1 = (const float*)d_in[12];
    const float* nb1 = (const float*)d_in[13];
    const float* nW2 = (const float*)d_in[14];
    const float* nb2 = (const float*)d_in[15];

    float *es, *m, *intra, *hnode, *xA, *xB, *pos, *posacc, *deg, *invden;
    int *srcI, *dstI;
    cudaGetSymbolAddress((void**)&es, g_es);
    cudaGetSymbolAddress((void**)&m, g_m);
    cudaGetSymbolAddress((void**)&intra, g_intra);
    cudaGetSymbolAddress((void**)&hnode, g_hnode);
    cudaGetSymbolAddress((void**)&xA, g_xA);
    cudaGetSymbolAddress((void**)&xB, g_xB);
    cudaGetSymbolAddress((void**)&pos, g_pos);
    cudaGetSymbolAddress((void**)&posacc, g_posacc);
    cudaGetSymbolAddress((void**)&deg, g_deg);
    cudaGetSymbolAddress((void**)&invden, g_invden);
    cudaGetSymbolAddress((void**)&srcI, g_src);
    cudaGetSymbolAddress((void**)&dstI, g_dst);

    const int T = 256;

    // normalize edge_index to int32 src/dst
    detect_idx_kernel<<<1, 1>>>(ei_raw);
    cvt_idx_kernel<<<(NE + T - 1) / T, T>>>(ei_raw, srcI, dstI);

    // degree + invden (deterministic, recomputed each call)
    zero_kernel<<<(NN + T - 1) / T, T>>>(deg, NN);
    deg_kernel<<<(NE + T - 1) / T, T>>>(dstI, deg);
    invden_kernel<<<(NN + T - 1) / T, T>>>(deg, invden);
    // pos init
    cudaMemcpyAsync(pos, pos_in, (size_t)NN * 3 * sizeof(float), cudaMemcpyDeviceToDevice);

    dim3 gE1((NE + 127) / 128, 1);   // N=128 edge gemms
    dim3 gE2((NE + 127) / 128, 2);   // N=256 edge gemms
    dim3 gN1((NN + 127) / 128, 1);
    dim3 gN2((NN + 127) / 128, 2);

    const float* xc = x_in;
    for (int l = 0; l < NL; l++) {
        zero_kernel<<<(NN * 128 + T - 1) / T, T>>>(intra, NN * 128);
        zero_kernel<<<(NN * 3 + T - 1) / T, T>>>(posacc, NN * 3);

        // message MLP layer 1: [E,384] (gathered) @ [384,128] -> relu -> es (m_h)
        gemm_kernel<1, true><<<gE1, T>>>(NE, 3 * HD, HD,
            xc, ea, srcI, dstI, nullptr, nullptr,
            mW1 + (size_t)l * 3 * HD * HD, mb1 + (size_t)l * HD, es);
        // message MLP layer 2: [E,128] @ [128,128] -> m
        gemm_kernel<0, false><<<gE1, T>>>(NE, HD, HD,
            es, nullptr, nullptr, nullptr, nullptr, nullptr,
            mW2 + (size_t)l * HD * HD, mb2 + (size_t)l * HD, m);
        // accel MLP layer 1: [E,128] @ [128,256] -> relu -> es (a_h)
        gemm_kernel<0, true><<<gE2, T>>>(NE, HD, 2 * HD,
            m, nullptr, nullptr, nullptr, nullptr, nullptr,
            aW1 + (size_t)l * HD * 2 * HD, ab1 + (size_t)l * 2 * HD, es);
        // accel MLP layer 2 (dot) + equivariant pos accumulation
        w_acc_kernel<<<(NE + 7) / 8, T>>>(es, aW2 + (size_t)l * 2 * HD, ab2 + l,
                                          pos, srcI, dstI, posacc);
        // intra = segment_sum(m, dst)
        scatter_m_kernel<<<((size_t)NE * 32 + T - 1) / T, T>>>(m, dstI, intra);
        // pos += posacc * invden
        posupd_kernel<<<(NN * 3 + T - 1) / T, T>>>(posacc, invden, pos);
        // node MLP layer 1: [N,256] (cat(x, intra*invden)) @ [256,256] -> relu
        gemm_kernel<2, true><<<gN2, T>>>(NN, 2 * HD, 2 * HD,
            xc, nullptr, nullptr, nullptr, intra, invden,
            nW1 + (size_t)l * 2 * HD * 2 * HD, nb1 + (size_t)l * 2 * HD, hnode);
        // node MLP layer 2: [N,256] @ [256,128] -> x_next
        float* xn = (l & 1) ? xB : xA;
        gemm_kernel<0, false><<<gN1, T>>>(NN, 2 * HD, HD,
            hnode, nullptr, nullptr, nullptr, nullptr, nullptr,
            nW2 + (size_t)l * 2 * HD * HD, nb2 + (size_t)l * HD, xn);
        xc = xn;
    }

    cudaMemcpyAsync(d_out, pos, (size_t)NN * 3 * sizeof(float), cudaMemcpyDeviceToDevice);
}

// round 6
// speedup vs baseline: 1.2083x; 1.2083x over previous
#include <cuda_runtime.h>
#include <cuda_bf16.h>
#include <cstdint>

#define NN 50000      // nodes
#define NE 500000     // edges
#define HD 128        // hidden dim
#define NL 3          // layers

// ---------------- scratch (device globals; no allocation allowed) ----------------
__device__ float g_es[(size_t)NE * 256];     // edge scratch: EaW [E,128], later a_h [E,256]
__device__ float g_m[(size_t)NE * 128];      // message output m [E,128]
__device__ float g_intra[(size_t)NN * 128];  // segment_sum(m) per node
__device__ float g_hnode[(size_t)NN * 256];  // node MLP hidden
__device__ float g_xA[(size_t)NN * 128];
__device__ float g_xB[(size_t)NN * 128];
__device__ float g_xd[(size_t)NN * 128];     // x @ W1a + b1
__device__ float g_xs[(size_t)NN * 128];     // x @ W1b
__device__ float g_pos[NN * 3];
__device__ float g_posacc[NN * 3];
__device__ float g_deg[NN];
__device__ float g_invden[NN];
__device__ float g_zb[256];                  // zero bias
__device__ int   g_src[NE];
__device__ int   g_dst[NE];
__device__ int   g_is64;

// ---------------- index dtype detection + normalization ----------------
__global__ void detect_idx_kernel(const int* __restrict__ ei) {
    int nz = 0;
    for (int i = 0; i < 128; i++)
        if (ei[2 * i + 1] != 0) nz++;
    g_is64 = (nz == 0) ? 1 : 0;
}

__global__ void cvt_idx_kernel(const int* __restrict__ ei,
                               int* __restrict__ srcO, int* __restrict__ dstO) {
    int e = blockIdx.x * blockDim.x + threadIdx.x;
    if (e >= NE) return;
    if (g_is64) {
        srcO[e] = ei[2 * e];
        dstO[e] = ei[2 * NE + 2 * e];
    } else {
        srcO[e] = ei[e];
        dstO[e] = ei[NE + e];
    }
}

// ---------------- helpers ----------------
__global__ void zero_kernel(float* p, int n) {
    int i = blockIdx.x * blockDim.x + threadIdx.x;
    if (i < n) p[i] = 0.0f;
}

__global__ void deg_kernel(const int* __restrict__ dst, float* __restrict__ deg) {
    int e = blockIdx.x * blockDim.x + threadIdx.x;
    if (e < NE) atomicAdd(&deg[dst[e]], 1.0f);
}

__global__ void invden_kernel(const float* __restrict__ deg, float* __restrict__ invden) {
    int n = blockIdx.x * blockDim.x + threadIdx.x;
    if (n < NN) invden[n] = 1.0f / fmaxf(deg[n], 1.0f);
}

__global__ void posupd_kernel(const float* __restrict__ posacc,
                              const float* __restrict__ invden,
                              float* __restrict__ pos) {
    int i = blockIdx.x * blockDim.x + threadIdx.x;
    if (i < NN * 3) pos[i] += posacc[i] * invden[i / 3];
}

// scatter m[e,:] into intra[dst[e],:] (one warp per edge, 4 cols per lane)
__global__ void scatter_m_kernel(const float* __restrict__ m,
                                 const int* __restrict__ dst,
                                 float* __restrict__ intra) {
    int t = blockIdx.x * blockDim.x + threadIdx.x;
    int e = t >> 5;
    if (e >= NE) return;
    int c = (t & 31) * 4;
    float4 v = *(const float4*)(m + (size_t)e * 128 + c);
    float* p = intra + (size_t)dst[e] * 128 + c;
    atomicAdd(p + 0, v.x);
    atomicAdd(p + 1, v.y);
    atomicAdd(p + 2, v.z);
    atomicAdd(p + 3, v.w);
}

// w = a_h[e,:] . W2 + b2 ; acc_e = w * rel/dist ; atomic-accumulate into posacc[dst]
__global__ __launch_bounds__(256) void w_acc_kernel(
    const float* __restrict__ ah,        // [E,256]
    const float* __restrict__ W2,        // [256]
    const float* __restrict__ b2p,       // [1]
    const float* __restrict__ pos,       // [N,3]
    const int* __restrict__ srcI,
    const int* __restrict__ dstI,
    float* __restrict__ posacc)
{
    __shared__ float w2s[256];
    int tid = threadIdx.x;
    w2s[tid] = W2[tid];
    __syncthreads();
    int lane = tid & 31;
    int e = blockIdx.x * 8 + (tid >> 5);
    if (e >= NE) return;
    const float* row = ah + (size_t)e * 256;
    float s = 0.0f;
    #pragma unroll
    for (int k = 0; k < 256; k += 32) s += row[k + lane] * w2s[k + lane];
    #pragma unroll
    for (int o = 16; o; o >>= 1) s += __shfl_xor_sync(0xffffffffu, s, o);
    if (lane == 0) {
        float w = s + b2p[0];
        int sI = srcI[e], dI = dstI[e];
        float rx = pos[sI * 3 + 0] - pos[dI * 3 + 0];
        float ry = pos[sI * 3 + 1] - pos[dI * 3 + 1];
        float rz = pos[sI * 3 + 2] - pos[dI * 3 + 2];
        float d = sqrtf(rx * rx + ry * ry + rz * rz);
        float f = w / d;
        atomicAdd(&posacc[dI * 3 + 0], f * rx);
        atomicAdd(&posacc[dI * 3 + 1], f * ry);
        atomicAdd(&posacc[dI * 3 + 2], f * rz);
    }
}

// ---------------- generic fused-gather SGEMM ----------------
// C[M,N] = act(A'[M,K] @ B[K,N] + bias), 128x128x8 tiles, 8x8 microtiles.
// MODE 0: A' = A (row-major, lda=K)
// MODE 2: A'[n, k] = k<128 ? A[n,k] : intra[n,k-128]*invden[n]
// MODE 3: A'[e, k] = relu(A(=Xd)[dst[e],k] + intra(=Xs)[src[e],k] + EA(=EaW)[e,k])
template <int MODE, bool RELU>
__global__ __launch_bounds__(256) void gemm_kernel(
    int M, int K, int N,
    const float* __restrict__ A,
    const float* __restrict__ EA,
    const int* __restrict__ srcI,
    const int* __restrict__ dstI,
    const float* __restrict__ intra,
    const float* __restrict__ invden,
    const float* __restrict__ B,
    const float* __restrict__ bias,
    float* __restrict__ C)
{
    const int BM = 128, BN = 128, BK = 8;
    __shared__ float As[BK][BM];
    __shared__ float Bs[BK][BN];

    int tid = threadIdx.x;
    int brow = blockIdx.x * BM;
    int bcol = blockIdx.y * BN;

    int a_row = tid >> 1;        // 0..127
    int a_k4 = (tid & 1) * 4;    // 0 or 4
    int b_row = tid >> 5;        // 0..7
    int b_col4 = (tid & 31) * 4; // 0..124

    int ty = tid >> 4, tx = tid & 15;

    float acc[8][8];
    #pragma unroll
    for (int i = 0; i < 8; i++)
        #pragma unroll
        for (int j = 0; j < 8; j++) acc[i][j] = 0.0f;

    for (int kt = 0; kt < K; kt += BK) {
        float4 av = make_float4(0.f, 0.f, 0.f, 0.f);
        int grow = brow + a_row;
        if (grow < M) {
            int gk = kt + a_k4;
            if (MODE == 0) {
                av = *(const float4*)(A + (size_t)grow * K + gk);
            } else if (MODE == 2) {
                if (gk < HD) {
                    av = *(const float4*)(A + (size_t)grow * HD + gk);
                } else {
                    float iv = invden[grow];
                    float4 t = *(const float4*)(intra + (size_t)grow * HD + (gk - HD));
                    av = make_float4(t.x * iv, t.y * iv, t.z * iv, t.w * iv);
                }
            } else { // MODE 3: relu(Xd[dst] + Xs[src] + EaW)
                int rd = dstI[grow];
                int rs = srcI[grow];
                float4 d = *(const float4*)(A + (size_t)rd * HD + gk);
                float4 s = *(const float4*)(intra + (size_t)rs * HD + gk);
                float4 e = *(const float4*)(EA + (size_t)grow * HD + gk);
                av.x = fmaxf(d.x + s.x + e.x, 0.f);
                av.y = fmaxf(d.y + s.y + e.y, 0.f);
                av.z = fmaxf(d.z + s.z + e.z, 0.f);
                av.w = fmaxf(d.w + s.w + e.w, 0.f);
            }
        }
        As[a_k4 + 0][a_row] = av.x;
        As[a_k4 + 1][a_row] = av.y;
        As[a_k4 + 2][a_row] = av.z;
        As[a_k4 + 3][a_row] = av.w;

        float4 bv = *(const float4*)(B + (size_t)(kt + b_row) * N + bcol + b_col4);
        *(float4*)(&Bs[b_row][b_col4]) = bv;

        __syncthreads();

        #pragma unroll
        for (int kk = 0; kk < BK; kk++) {
            float ra[8], rb[8];
            #pragma unroll
            for (int i = 0; i < 8; i++) ra[i] = As[kk][ty * 8 + i];
            #pragma unroll
            for (int j = 0; j < 8; j++) rb[j] = Bs[kk][tx * 8 + j];
            #pragma unroll
            for (int i = 0; i < 8; i++)
                #pragma unroll
                for (int j = 0; j < 8; j++)
                    acc[i][j] = fmaf(ra[i], rb[j], acc[i][j]);
        }
        __syncthreads();
    }

    // epilogue
    float bb[8];
    #pragma unroll
    for (int j = 0; j < 8; j++) bb[j] = bias[bcol + tx * 8 + j];

    #pragma unroll
    for (int i = 0; i < 8; i++) {
        int row = brow + ty * 8 + i;
        if (row >= M) continue;
        float* crow = C + (size_t)row * N + bcol + tx * 8;
        #pragma unroll
        for (int j = 0; j < 8; j += 4) {
            float4 v;
            v.x = acc[i][j + 0] + bb[j + 0];
            v.y = acc[i][j + 1] + bb[j + 1];
            v.z = acc[i][j + 2] + bb[j + 2];
            v.w = acc[i][j + 3] + bb[j + 3];
            if (RELU) {
                v.x = fmaxf(v.x, 0.f);
                v.y = fmaxf(v.y, 0.f);
                v.z = fmaxf(v.z, 0.f);
                v.w = fmaxf(v.w, 0.f);
            }
            *(float4*)(crow + j) = v;
        }
    }
}

// ---------------- host launch ----------------
extern "C" void kernel_launch(void* const* d_in, const int* in_sizes, int n_in,
                              void* d_out, int out_size) {
    const float* x_in   = (const float*)d_in[0];
    const int* ei_raw   = (const int*)d_in[1];   // int32 view; dtype resolved on device
    const float* ea     = (const float*)d_in[2];
    const float* pos_in = (const float*)d_in[3];
    const float* mW1 = (const float*)d_in[4];
    const float* mb1 = (const float*)d_in[5];
    const float* mW2 = (const float*)d_in[6];
    const float* mb2 = (const float*)d_in[7];
    const float* aW1 = (const float*)d_in[8];
    const float* ab1 = (const float*)d_in[9];
    const float* aW2 = (const float*)d_in[10];
    const float* ab2 = (const float*)d_in[11];
    const float* nW1 = (const float*)d_in[12];
    const float* nb1 = (const float*)d_in[13];
    const float* nW2 = (const float*)d_in[14];
    const float* nb2 = (const float*)d_in[15];

    float *es, *m, *intra, *hnode, *xA, *xB, *xd, *xs, *pos, *posacc, *deg, *invden, *zb;
    int *srcI, *dstI;
    cudaGetSymbolAddress((void**)&es, g_es);
    cudaGetSymbolAddress((void**)&m, g_m);
    cudaGetSymbolAddress((void**)&intra, g_intra);
    cudaGetSymbolAddress((void**)&hnode, g_hnode);
    cudaGetSymbolAddress((void**)&xA, g_xA);
    cudaGetSymbolAddress((void**)&xB, g_xB);
    cudaGetSymbolAddress((void**)&xd, g_xd);
    cudaGetSymbolAddress((void**)&xs, g_xs);
    cudaGetSymbolAddress((void**)&pos, g_pos);
    cudaGetSymbolAddress((void**)&posacc, g_posacc);
    cudaGetSymbolAddress((void**)&deg, g_deg);
    cudaGetSymbolAddress((void**)&invden, g_invden);
    cudaGetSymbolAddress((void**)&zb, g_zb);
    cudaGetSymbolAddress((void**)&srcI, g_src);
    cudaGetSymbolAddress((void**)&dstI, g_dst);

    const int T = 256;

    // normalize edge_index to int32 src/dst
    detect_idx_kernel<<<1, 1>>>(ei_raw);
    cvt_idx_kernel<<<(NE + T - 1) / T, T>>>(ei_raw, srcI, dstI);

    // degree + invden
    zero_kernel<<<(NN + T - 1) / T, T>>>(deg, NN);
    zero_kernel<<<1, 256>>>(zb, 256);
    deg_kernel<<<(NE + T - 1) / T, T>>>(dstI, deg);
    invden_kernel<<<(NN + T - 1) / T, T>>>(deg, invden);
    cudaMemcpyAsync(pos, pos_in, (size_t)NN * 3 * sizeof(float), cudaMemcpyDeviceToDevice);

    dim3 gE1((NE + 127) / 128, 1);   // N=128 edge gemms
    dim3 gE2((NE + 127) / 128, 2);   // N=256 edge gemms
    dim3 gN1((NN + 127) / 128, 1);
    dim3 gN2((NN + 127) / 128, 2);

    const float* xc = x_in;
    for (int l = 0; l < NL; l++) {
        zero_kernel<<<(NN * 128 + T - 1) / T, T>>>(intra, NN * 128);
        zero_kernel<<<(NN * 3 + T - 1) / T, T>>>(posacc, NN * 3);

        // --- message MLP layer 1, restructured ---
        // W1 rows: [0:128) -> x_i(dst) part, [128:256) -> x_j(src), [256:384) -> edge_attr
        const float* W1 = mW1 + (size_t)l * 3 * HD * HD;
        // Xd = xc @ W1a + b1   [N,128]
        gemm_kernel<0, false><<<gN1, T>>>(NN, HD, HD,
            xc, nullptr, nullptr, nullptr, nullptr, nullptr,
            W1, mb1 + (size_t)l * HD, xd);
        // Xs = xc @ W1b        [N,128]
        gemm_kernel<0, false><<<gN1, T>>>(NN, HD, HD,
            xc, nullptr, nullptr, nullptr, nullptr, nullptr,
            W1 + (size_t)HD * HD, zb, xs);
        // EaW = ea @ W1c       [E,128] (stored in es)
        gemm_kernel<0, false><<<gE1, T>>>(NE, HD, HD,
            ea, nullptr, nullptr, nullptr, nullptr, nullptr,
            W1 + (size_t)2 * HD * HD, zb, es);
        // message MLP layer 2 with fused m_h = relu(Xd[dst]+Xs[src]+EaW):
        // m = m_h @ W2 + b2    [E,128]
        gemm_kernel<3, false><<<gE1, T>>>(NE, HD, HD,
            xd, es, srcI, dstI, xs, nullptr,
            mW2 + (size_t)l * HD * HD, mb2 + (size_t)l * HD, m);
        // accel MLP layer 1: [E,128] @ [128,256] -> relu -> es (a_h)
        gemm_kernel<0, true><<<gE2, T>>>(NE, HD, 2 * HD,
            m, nullptr, nullptr, nullptr, nullptr, nullptr,
            aW1 + (size_t)l * HD * 2 * HD, ab1 + (size_t)l * 2 * HD, es);
        // accel MLP layer 2 (dot) + equivariant pos accumulation
        w_acc_kernel<<<(NE + 7) / 8, T>>>(es, aW2 + (size_t)l * 2 * HD, ab2 + l,
                                          pos, srcI, dstI, posacc);
        // intra = segment_sum(m, dst)
        scatter_m_kernel<<<((size_t)NE * 32 + T - 1) / T, T>>>(m, dstI, intra);
        // pos += posacc * invden
        posupd_kernel<<<(NN * 3 + T - 1) / T, T>>>(posacc, invden, pos);
        // node MLP layer 1: [N,256] (cat(x, intra*invden)) @ [256,256] -> relu
        gemm_kernel<2, true><<<gN2, T>>>(NN, 2 * HD, 2 * HD,
            xc, nullptr, nullptr, nullptr, intra, invden,
            nW1 + (size_t)l * 2 * HD * 2 * HD, nb1 + (size_t)l * 2 * HD, hnode);
        // node MLP layer 2: [N,256] @ [256,128] -> x_next
        float* xn = (l & 1) ? xB : xA;
        gemm_kernel<0, false><<<gN1, T>>>(NN, 2 * HD, HD,
            hnode, nullptr, nullptr, nullptr, nullptr, nullptr,
            nW2 + (size_t)l * 2 * HD * HD, nb2 + (size_t)l * HD, xn);
        xc = xn;
    }

    cudaMemcpyAsync(d_out, pos, (size_t)NN * 3 * sizeof(float), cudaMemcpyDeviceToDevice);
}